// round 1
// baseline (speedup 1.0000x reference)
#include <cuda_runtime.h>

#define TSTEPS  1024
#define BATCH   64
#define IN_DIM  256
#define HID_DIM 512
#define OUT_DIM 256
#define KDIM    768
#define NCTA    128
#define NTHR    256

// ---- device-wide barrier state (graph-replay safe: count self-resets) ----
__device__ unsigned g_bar_count = 0;
__device__ volatile unsigned g_bar_gen = 0;

__device__ __forceinline__ void grid_barrier() {
    __syncthreads();
    if (threadIdx.x == 0) {
        __threadfence();                       // release my writes
        unsigned g = g_bar_gen;                // read gen BEFORE arriving (safe: gen
                                               // can't bump until I arrive)
        if (atomicAdd(&g_bar_count, 1u) == NCTA - 1) {
            g_bar_count = 0;
            __threadfence();                   // reset ordered before gen bump
            g_bar_gen = g + 1;
        } else {
            while (g_bar_gen == g) {}
            __threadfence();                   // acquire others' writes
        }
    }
    __syncthreads();
}

// Persistent RNN kernel.
// Partition: 128 CTAs = 64 column-groups x 2 batch-halves.
//   column-group g owns h-cols [g*8, g*8+8) and r-cols [g*4, g*4+4)
//   batch half owns 32 batch rows; warp w within CTA owns 4 of them.
//   lane = k-slice: lane owns k in {4*lane + 128*i}.
// Weights for the owned columns live in smem for the entire kernel.
// h/r histories live in d_out (they are the outputs anyway) and double as the
// inter-CTA exchange buffers; addresses are time-indexed so L1 staleness can't
// occur (every read address is first-touch).
//
// Iteration it (0..T):  h[it+1] = relu(x[it]·Wx + h[it]·Wh + b_ih)   (it <  T)
//                       r[it]   = relu(h[it]·Wo_h + r[it-1]·Wo_r + b_ho) (it >= 1)
// Both parts read only pre-barrier state -> ONE grid barrier per iteration.
__global__ void __launch_bounds__(NTHR, 1)
rnn_persistent_kernel(const float* __restrict__ X,    // [64][1024][256]
                      const float* __restrict__ H0,   // [64][512]
                      const float* __restrict__ R0,   // [64][256]
                      const float* __restrict__ Wih,  // [512][768]
                      const float* __restrict__ Bih,  // [512]
                      const float* __restrict__ Who,  // [256][768]
                      const float* __restrict__ Bho,  // [256]
                      float* __restrict__ Rout,       // [64][1025][256]
                      float* __restrict__ Hout)       // [64][1025][512]
{
    __shared__ float W1s[8][KDIM];   // W_ih rows jh0..jh0+7   (k: 0..255 = x, 256..767 = h)
    __shared__ float W2s[4][KDIM];   // W_ho rows jr0..jr0+3   (k: 0..511 = h, 512..767 = r)
    __shared__ float bih_s[8];
    __shared__ float bho_s[4];

    const int tid  = threadIdx.x;
    const int cta  = blockIdx.x;
    const int grp  = cta >> 1;        // 0..63 column group
    const int half = cta & 1;         // batch half
    const int b0   = half * 32;
    const int jh0  = grp * 8;
    const int jr0  = grp * 4;
    const int wrp  = tid >> 5;        // 0..7: which 4-batch subgroup
    const int lane = tid & 31;        // k-slice

    // ---- load stationary weight slices into smem (coalesced over k) ----
    for (int idx = tid; idx < 8 * KDIM; idx += NTHR) {
        int j = idx / KDIM, k = idx % KDIM;
        W1s[j][k] = Wih[(jh0 + j) * KDIM + k];
    }
    for (int idx = tid; idx < 4 * KDIM; idx += NTHR) {
        int j = idx / KDIM, k = idx % KDIM;
        W2s[j][k] = Who[(jr0 + j) * KDIM + k];
    }
    if (tid < 8) bih_s[tid] = Bih[jh0 + tid];
    if (tid < 4) bho_s[tid] = Bho[jr0 + tid];

    // ---- write t=0 states into the output/exchange buffers ----
    for (int idx = tid; idx < 32 * 8; idx += NTHR) {
        int b = b0 + (idx >> 3), jj = idx & 7;
        Hout[(b * 1025) * HID_DIM + jh0 + jj] = H0[b * HID_DIM + jh0 + jj];
    }
    for (int idx = tid; idx < 32 * 4; idx += NTHR) {
        int b = b0 + (idx >> 2), jj = idx & 3;
        Rout[(b * 1025) * OUT_DIM + jr0 + jj] = R0[b * OUT_DIM + jr0 + jj];
    }

    grid_barrier();

    const int bb0 = b0 + wrp * 4;     // this warp's first batch row

    for (int it = 0; it <= TSTEPS; ++it) {
        float hacc[4][8];
        float racc[4][4];
#pragma unroll
        for (int b = 0; b < 4; ++b) {
#pragma unroll
            for (int j = 0; j < 8; ++j) hacc[b][j] = 0.f;
#pragma unroll
            for (int j = 0; j < 4; ++j) racc[b][j] = 0.f;
        }

        // ---- part 1: x contribution to h (k = 0..255) ----
        if (it < TSTEPS) {
#pragma unroll
            for (int i = 0; i < 2; ++i) {
                const int k = 4 * lane + 128 * i;
                float4 wv[8];
#pragma unroll
                for (int j = 0; j < 8; ++j) wv[j] = *(const float4*)&W1s[j][k];
#pragma unroll
                for (int b = 0; b < 4; ++b) {
                    const float4 a = *(const float4*)&X[((bb0 + b) * TSTEPS + it) * IN_DIM + k];
#pragma unroll
                    for (int j = 0; j < 8; ++j)
                        hacc[b][j] += a.x * wv[j].x + a.y * wv[j].y
                                    + a.z * wv[j].z + a.w * wv[j].w;
                }
            }
        }

        // ---- part 2: h[it] feeds BOTH h-dot (W_ih k=256..767) and r-dot (W_ho k=0..511) ----
#pragma unroll
        for (int i = 0; i < 4; ++i) {
            const int hk = 4 * lane + 128 * i;   // 0..511
            const int k  = hk + 256;
            float4 w1[8], w2[4];
#pragma unroll
            for (int j = 0; j < 8; ++j) w1[j] = *(const float4*)&W1s[j][k];
#pragma unroll
            for (int j = 0; j < 4; ++j) w2[j] = *(const float4*)&W2s[j][hk];
#pragma unroll
            for (int b = 0; b < 4; ++b) {
                const float4 a = *(const float4*)&Hout[((bb0 + b) * 1025 + it) * HID_DIM + hk];
#pragma unroll
                for (int j = 0; j < 8; ++j)
                    hacc[b][j] += a.x * w1[j].x + a.y * w1[j].y
                                + a.z * w1[j].z + a.w * w1[j].w;
#pragma unroll
                for (int j = 0; j < 4; ++j)
                    racc[b][j] += a.x * w2[j].x + a.y * w2[j].y
                                + a.z * w2[j].z + a.w * w2[j].w;
            }
        }

        // ---- part 3: r[it-1] contribution to r (W_ho k = 512..767) ----
        if (it >= 1) {
#pragma unroll
            for (int i = 0; i < 2; ++i) {
                const int rk = 4 * lane + 128 * i;   // 0..255
                float4 w2[4];
#pragma unroll
                for (int j = 0; j < 4; ++j) w2[j] = *(const float4*)&W2s[j][512 + rk];
#pragma unroll
                for (int b = 0; b < 4; ++b) {
                    const float4 a = *(const float4*)&Rout[((bb0 + b) * 1025 + (it - 1)) * OUT_DIM + rk];
#pragma unroll
                    for (int j = 0; j < 4; ++j)
                        racc[b][j] += a.x * w2[j].x + a.y * w2[j].y
                                    + a.z * w2[j].z + a.w * w2[j].w;
                }
            }
        }

        // ---- butterfly all-reduce over the 32 k-slices; lane a keeps acc a ----
        float myH = 0.f, myR = 0.f;
#pragma unroll
        for (int a = 0; a < 32; ++a) {
            float s = hacc[a >> 3][a & 7];
            s += __shfl_xor_sync(0xffffffffu, s, 1);
            s += __shfl_xor_sync(0xffffffffu, s, 2);
            s += __shfl_xor_sync(0xffffffffu, s, 4);
            s += __shfl_xor_sync(0xffffffffu, s, 8);
            s += __shfl_xor_sync(0xffffffffu, s, 16);
            if (lane == a) myH = s;
        }
#pragma unroll
        for (int a = 0; a < 16; ++a) {
            float s = racc[a >> 2][a & 3];
            s += __shfl_xor_sync(0xffffffffu, s, 1);
            s += __shfl_xor_sync(0xffffffffu, s, 2);
            s += __shfl_xor_sync(0xffffffffu, s, 4);
            s += __shfl_xor_sync(0xffffffffu, s, 8);
            s += __shfl_xor_sync(0xffffffffu, s, 16);
            if (lane == a) myR = s;
        }

        // ---- bias + relu + store (lane -> (batch, col)) ----
        if (it < TSTEPS) {
            const int bl = lane >> 3, jj = lane & 7;
            const float v = fmaxf(myH + bih_s[jj], 0.f);
            Hout[((bb0 + bl) * 1025 + (it + 1)) * HID_DIM + jh0 + jj] = v;
        }
        if (it >= 1 && lane < 16) {
            const int bl = lane >> 2, jj = lane & 3;
            const float v = fmaxf(myR + bho_s[jj], 0.f);
            Rout[((bb0 + bl) * 1025 + it) * OUT_DIM + jr0 + jj] = v;
        }

        grid_barrier();
    }
}

extern "C" void kernel_launch(void* const* d_in, const int* in_sizes, int n_in,
                              void* d_out, int out_size) {
    const float* X   = (const float*)d_in[0];
    const float* H0  = (const float*)d_in[1];
    const float* R0  = (const float*)d_in[2];
    const float* Wih = (const float*)d_in[3];
    const float* Bih = (const float*)d_in[4];
    const float* Who = (const float*)d_in[5];
    const float* Bho = (const float*)d_in[6];

    float* Rout = (float*)d_out;                                   // [64][1025][256]
    float* Hout = (float*)d_out + (size_t)BATCH * 1025 * OUT_DIM;  // [64][1025][512]

    rnn_persistent_kernel<<<NCTA, NTHR>>>(X, H0, R0, Wih, Bih, Who, Bho, Rout, Hout);
}

// round 2
// speedup vs baseline: 1.1551x; 1.1551x over previous
#include <cuda_runtime.h>

#define TSTEPS  1024
#define BATCH   64
#define IN_DIM  256
#define HID_DIM 512
#define OUT_DIM 256
#define KDIM    768
#define NCTA    128
#define NTHR    512

// ---- device-wide barrier state (graph-replay safe: count self-resets) ----
__device__ unsigned g_bar_count = 0;
__device__ volatile unsigned g_bar_gen = 0;

__device__ __forceinline__ void grid_barrier() {
    __syncthreads();
    if (threadIdx.x == 0) {
        __threadfence();                       // release my writes
        unsigned g = g_bar_gen;                // read gen BEFORE arriving
        if (atomicAdd(&g_bar_count, 1u) == NCTA - 1) {
            g_bar_count = 0;
            __threadfence();                   // reset ordered before gen bump
            g_bar_gen = g + 1;
        } else {
            while (g_bar_gen == g) {}
            __threadfence();                   // acquire others' writes
        }
    }
    __syncthreads();
}

// Persistent RNN kernel, v2.
// 128 CTAs = 64 column-groups x 2 batch-halves. CTA = 512 threads = 16 warps.
//   column-group g owns h-cols [g*8, g*8+8) and r-cols [g*4, g*4+4)
//   warp = (col-half ch in {0,1}) x (batch-oct, 4 rows each)
//   warp computes 6 cols (4 h + 2 r) x 4 batch rows; lane = k-slice (4*lane + 128*i).
// One grid barrier per iteration (both dots read only pre-barrier state).
// Reduction: transpose-butterfly — 31 shuffles reduce ALL 24 accumulators,
// leaving output L on lane L.
__global__ void __launch_bounds__(NTHR, 1)
rnn_persistent_kernel(const float* __restrict__ X,    // [64][1024][256]
                      const float* __restrict__ H0,   // [64][512]
                      const float* __restrict__ R0,   // [64][256]
                      const float* __restrict__ Wih,  // [512][768]
                      const float* __restrict__ Bih,  // [512]
                      const float* __restrict__ Who,  // [256][768]
                      const float* __restrict__ Bho,  // [256]
                      float* __restrict__ Rout,       // [64][1025][256]
                      float* __restrict__ Hout)       // [64][1025][512]
{
    __shared__ float W1s[8][KDIM];   // W_ih rows jh0..jh0+7 (k: 0..255 x | 256..767 h)
    __shared__ float W2s[4][KDIM];   // W_ho rows jr0..jr0+3 (k: 0..511 h | 512..767 r)
    __shared__ float bih_s[8];
    __shared__ float bho_s[4];

    const int tid  = threadIdx.x;
    const int cta  = blockIdx.x;
    const int grp  = cta >> 1;        // 0..63 column group
    const int half = cta & 1;         // batch half
    const int b0   = half * 32;
    const int jh0  = grp * 8;
    const int jr0  = grp * 4;
    const int wrp  = tid >> 5;
    const int lane = tid & 31;
    const int ch   = wrp >> 3;        // col half: 4 h-cols + 2 r-cols
    const int boct = wrp & 7;         // batch oct (4 rows)
    const int bb0  = b0 + boct * 4;

    // ---- load stationary weight slices into smem (coalesced over k) ----
    for (int idx = tid; idx < 8 * KDIM; idx += NTHR) {
        int j = idx / KDIM, k = idx % KDIM;
        W1s[j][k] = Wih[(jh0 + j) * KDIM + k];
    }
    for (int idx = tid; idx < 4 * KDIM; idx += NTHR) {
        int j = idx / KDIM, k = idx % KDIM;
        W2s[j][k] = Who[(jr0 + j) * KDIM + k];
    }
    if (tid < 8) bih_s[tid] = Bih[jh0 + tid];
    if (tid < 4) bho_s[tid] = Bho[jr0 + tid];

    // ---- write t=0 states into the output/exchange buffers ----
    for (int idx = tid; idx < 32 * 8; idx += NTHR) {
        int b = b0 + (idx >> 3), jj = idx & 7;
        Hout[(size_t)(b * 1025) * HID_DIM + jh0 + jj] = H0[b * HID_DIM + jh0 + jj];
    }
    for (int idx = tid; idx < 32 * 4; idx += NTHR) {
        int b = b0 + (idx >> 2), jj = idx & 3;
        Rout[(size_t)(b * 1025) * OUT_DIM + jr0 + jj] = R0[b * OUT_DIM + jr0 + jj];
    }

    grid_barrier();

    for (int it = 0; it <= TSTEPS; ++it) {
        // A[b*6 + c]: c in 0..3 = h-col (jh0 + ch*4 + c), c in 4..5 = r-col (jr0 + ch*2 + c-4)
        float A[24];
#pragma unroll
        for (int i = 0; i < 24; ++i) A[i] = 0.f;

        // ---- part 1: x contribution to h (k = 0..255) ----
        if (it < TSTEPS) {
#pragma unroll
            for (int i = 0; i < 2; ++i) {
                const int k = 4 * lane + 128 * i;
                float4 w[4];
#pragma unroll
                for (int c = 0; c < 4; ++c) w[c] = *(const float4*)&W1s[ch * 4 + c][k];
#pragma unroll
                for (int b = 0; b < 4; ++b) {
                    const float4 a = *(const float4*)&X[((size_t)(bb0 + b) * TSTEPS + it) * IN_DIM + k];
#pragma unroll
                    for (int c = 0; c < 4; ++c)
                        A[b * 6 + c] += a.x * w[c].x + a.y * w[c].y
                                      + a.z * w[c].z + a.w * w[c].w;
                }
            }
        }

        // ---- part 2: h[it] feeds BOTH h-dot (W_ih k=256..767) and r-dot (W_ho k=0..511) ----
#pragma unroll
        for (int i = 0; i < 4; ++i) {
            const int hk = 4 * lane + 128 * i;   // 0..511
            float4 w1[4], w2[2];
#pragma unroll
            for (int c = 0; c < 4; ++c) w1[c] = *(const float4*)&W1s[ch * 4 + c][256 + hk];
#pragma unroll
            for (int c = 0; c < 2; ++c) w2[c] = *(const float4*)&W2s[ch * 2 + c][hk];
#pragma unroll
            for (int b = 0; b < 4; ++b) {
                const float4 a = *(const float4*)&Hout[((size_t)(bb0 + b) * 1025 + it) * HID_DIM + hk];
#pragma unroll
                for (int c = 0; c < 4; ++c)
                    A[b * 6 + c] += a.x * w1[c].x + a.y * w1[c].y
                                  + a.z * w1[c].z + a.w * w1[c].w;
#pragma unroll
                for (int c = 0; c < 2; ++c)
                    A[b * 6 + 4 + c] += a.x * w2[c].x + a.y * w2[c].y
                                      + a.z * w2[c].z + a.w * w2[c].w;
            }
        }

        // ---- part 3: r[it-1] contribution to r (W_ho k = 512..767) ----
        if (it >= 1) {
#pragma unroll
            for (int i = 0; i < 2; ++i) {
                const int rk = 4 * lane + 128 * i;   // 0..255
                float4 w2[2];
#pragma unroll
                for (int c = 0; c < 2; ++c) w2[c] = *(const float4*)&W2s[ch * 2 + c][512 + rk];
#pragma unroll
                for (int b = 0; b < 4; ++b) {
                    const float4 a = *(const float4*)&Rout[((size_t)(bb0 + b) * 1025 + (it - 1)) * OUT_DIM + rk];
#pragma unroll
                    for (int c = 0; c < 2; ++c)
                        A[b * 6 + 4 + c] += a.x * w2[c].x + a.y * w2[c].y
                                          + a.z * w2[c].z + a.w * w2[c].w;
                }
            }
        }

        // ---- transpose-butterfly reduction: 31 shuffles, output L lands on lane L ----
#pragma unroll
        for (int off = 16; off >= 1; off >>= 1) {
#pragma unroll
            for (int i = 0; i < off; ++i) {
                const int j = i + off;
                const float vj = (j < 24) ? A[j] : 0.f;
                const float send = (lane & off) ? A[i] : vj;
                const float recv = __shfl_xor_sync(0xffffffffu, send, off);
                const float keep = (lane & off) ? vj : A[i];
                A[i] = keep + recv;
            }
        }
        // lane L (< 24) now holds the full sum for flat index L in A[0]

        if (lane < 24) {
            const int bl = lane / 6;
            const int c  = lane % 6;
            if (c < 4) {
                if (it < TSTEPS) {
                    const int col = jh0 + ch * 4 + c;
                    const float v = fmaxf(A[0] + bih_s[ch * 4 + c], 0.f);
                    Hout[((size_t)(bb0 + bl) * 1025 + (it + 1)) * HID_DIM + col] = v;
                }
            } else {
                if (it >= 1) {
                    const int cc  = c - 4;
                    const int col = jr0 + ch * 2 + cc;
                    const float v = fmaxf(A[0] + bho_s[ch * 2 + cc], 0.f);
                    Rout[((size_t)(bb0 + bl) * 1025 + it) * OUT_DIM + col] = v;
                }
            }
        }

        grid_barrier();
    }
}

extern "C" void kernel_launch(void* const* d_in, const int* in_sizes, int n_in,
                              void* d_out, int out_size) {
    const float* X   = (const float*)d_in[0];
    const float* H0  = (const float*)d_in[1];
    const float* R0  = (const float*)d_in[2];
    const float* Wih = (const float*)d_in[3];
    const float* Bih = (const float*)d_in[4];
    const float* Who = (const float*)d_in[5];
    const float* Bho = (const float*)d_in[6];

    float* Rout = (float*)d_out;                                   // [64][1025][256]
    float* Hout = (float*)d_out + (size_t)BATCH * 1025 * OUT_DIM;  // [64][1025][512]

    rnn_persistent_kernel<<<NCTA, NTHR>>>(X, H0, R0, Wih, Bih, Who, Bho, Rout, Hout);
}